// round 10
// baseline (speedup 1.0000x reference)
#include <cuda_runtime.h>
#include <cuda_fp16.h>
#include <mma.h>
#include <cstdint>

using namespace nvcuda;

#define SEQ 2048
#define EMB 2048
#define NB  2
#define NH  16
#define DH  128
#define MTOT (NB*SEQ)   // 4096
#define PLANE ((size_t)MTOT*EMB)

// ---------------- scratch (static device globals) ----------------
__device__ __half g_xh  [MTOT*EMB];
__device__ __half g_wh  [7][EMB*EMB];       // wq,wk,wv,wo,w0,sww,swv (contiguous)
__device__ __half g_qkvh[3][MTOT*EMB];      // plane0: qh [bh,t,d]; 1: kh [bh,s,d]; 2: v [b,s,E]
__device__ __half g_vp  [MTOT*EMB];         // [bh, d, s]
__device__ float  g_ctx [MTOT*EMB];
__device__ __half g_cth [MTOT*EMB];
__device__ float  g_xa  [MTOT*EMB];
__device__ __half g_x2h [MTOT*EMB];
__device__ __half g_hh  [MTOT*EMB];
__device__ __half g_wuh [2][MTOT*EMB];      // plane0: w, plane1: u (fp16)

__device__ __forceinline__ uint32_t smem_u32(const void* p) {
    uint32_t a;
    asm("{ .reg .u64 t; cvta.to.shared.u64 t, %1; cvt.u32.u64 %0, t; }" : "=r"(a) : "l"(p));
    return a;
}

// -------- fp16 wmma NT GEMM: 4 warps, 64x64 warp tiles, 3-stage cp.async ----
// CTA tile 128x128, BK=32. Fragment traffic 0.5 loads/MMA (was 0.75).
constexpr int BM = 128, BN = 128, PITCH = 40;          // pitch in halves
constexpr int STG_BYTES   = BM * PITCH * 2;            // 10240 per operand
constexpr int STAGE_BYTES = 2 * STG_BYTES;             // 20480 (A+B)
constexpr int NSTG = 3;
constexpr int SMEM_GEMM   = NSTG * STAGE_BYTES;        // 61440

// OMODE: 0 = fp32 out (opt RES); 1 = half plain out; 2 = QKV combined (3 planes)
template<int OMODE, bool RES>
__global__ void __launch_bounds__(128, 2)
gemm_h(int nk,
       const __half* __restrict__ A, int lda, int zRowA,
       const __half* __restrict__ B, int ldb, int zRowB,
       float* __restrict__ C, __half* __restrict__ Ch, int ldc,
       const float* __restrict__ Rres, float alphaA, float alphaB,
       long long sC)
{
    const int bn0 = blockIdx.x * BN;
    const int bm0 = blockIdx.y * BM;
    const int z = blockIdx.z;

    extern __shared__ __align__(128) char smem[];
    const int tid  = threadIdx.x;
    const int wid  = tid >> 5;
    const int lane = tid & 31;
    const int wm = (wid & 1) * 64;              // 2x2 warp grid, 64x64 tiles
    const int wn = (wid >> 1) * 64;

    const __half* Abase = A + (size_t)(z * zRowA + bm0) * lda;
    const __half* Bbase = B + (size_t)(z * zRowB + bn0) * ldb;
    const long long coff = (long long)z * sC;

    auto load_chunk = [&](int kc) {
        const int st = kc % NSTG;
        char* sA = smem + st * STAGE_BYTES;
        char* sB = sA + STG_BYTES;
        const __half* ag = Abase + kc * 32;
        const __half* bg = Bbase + kc * 32;
        #pragma unroll
        for (int i = 0; i < 4; i++) {            // 512 16B segs per operand
            int idx = i * 128 + tid;
            int row = idx >> 2, seg = idx & 3;
            uint32_t da = smem_u32(sA + row * (PITCH * 2) + seg * 16);
            const __half* srca = ag + (size_t)row * lda + seg * 8;
            asm volatile("cp.async.cg.shared.global [%0], [%1], 16;" :: "r"(da), "l"(srca));
            uint32_t db = smem_u32(sB + row * (PITCH * 2) + seg * 16);
            const __half* srcb = bg + (size_t)row * ldb + seg * 8;
            asm volatile("cp.async.cg.shared.global [%0], [%1], 16;" :: "r"(db), "l"(srcb));
        }
        asm volatile("cp.async.commit_group;" ::: "memory");
    };

    wmma::fragment<wmma::accumulator, 16, 16, 16, float> acc[4][4];
    #pragma unroll
    for (int mi = 0; mi < 4; mi++)
        #pragma unroll
        for (int ni = 0; ni < 4; ni++) {
            if (RES)
                wmma::load_matrix_sync(acc[mi][ni],
                    Rres + coff + (long long)(bm0 + wm + mi * 16) * ldc + (bn0 + wn + ni * 16),
                    ldc, wmma::mem_row_major);
            else
                wmma::fill_fragment(acc[mi][ni], 0.0f);
        }

    load_chunk(0);
    if (nk > 1) load_chunk(1);

    for (int kc = 0; kc < nk; kc++) {
        if (kc + 1 < nk)
            asm volatile("cp.async.wait_group 1;" ::: "memory");
        else
            asm volatile("cp.async.wait_group 0;" ::: "memory");
        __syncthreads();                          // single sync per chunk
        if (kc + 2 < nk) load_chunk(kc + 2);

        const __half* sA = (const __half*)(smem + (kc % NSTG) * STAGE_BYTES);
        const __half* sB = sA + BM * PITCH;
        #pragma unroll
        for (int kk = 0; kk < 2; kk++) {
            wmma::fragment<wmma::matrix_a, 16, 16, 16, __half, wmma::row_major> af[4];
            wmma::fragment<wmma::matrix_b, 16, 16, 16, __half, wmma::col_major> bf[4];
            #pragma unroll
            for (int mi = 0; mi < 4; mi++)
                wmma::load_matrix_sync(af[mi], sA + (wm + mi * 16) * PITCH + kk * 16, PITCH);
            #pragma unroll
            for (int ni = 0; ni < 4; ni++)
                wmma::load_matrix_sync(bf[ni], sB + (wn + ni * 16) * PITCH + kk * 16, PITCH);
            #pragma unroll
            for (int mi = 0; mi < 4; mi++)
                #pragma unroll
                for (int ni = 0; ni < 4; ni++)
                    wmma::mma_sync(acc[mi][ni], af[mi], bf[ni], acc[mi][ni]);
        }
    }

    const float alpha = (OMODE == 2) ? ((z == 1) ? alphaB : alphaA) : alphaA;
    if (alpha != 1.0f) {
        #pragma unroll
        for (int mi = 0; mi < 4; mi++)
            #pragma unroll
            for (int ni = 0; ni < 4; ni++)
                #pragma unroll
                for (int e = 0; e < acc[mi][ni].num_elements; e++)
                    acc[mi][ni].x[e] *= alpha;
    }

    if (OMODE == 0) {
        float* Cp = C + coff;
        #pragma unroll
        for (int mi = 0; mi < 4; mi++)
            #pragma unroll
            for (int ni = 0; ni < 4; ni++)
                wmma::store_matrix_sync(
                    Cp + (long long)(bm0 + wm + mi * 16) * ldc + (bn0 + wn + ni * 16),
                    acc[mi][ni], ldc, wmma::mem_row_major);
    } else {
        __syncthreads();                          // all MMAs done before smem reuse
        float* stg = (float*)smem + wid * 256;
        __half* Cp = (OMODE == 2) ? (Ch + (size_t)z * PLANE) : Ch;
        const bool hsplit = (OMODE == 2) && (z < 2);
        #pragma unroll
        for (int mi = 0; mi < 4; mi++)
            #pragma unroll
            for (int ni = 0; ni < 4; ni++) {
                wmma::store_matrix_sync(stg, acc[mi][ni], 16, wmma::mem_row_major);
                __syncwarp();
                const int r  = lane >> 1;
                const int cb = (lane & 1) * 8;
                __half2 hv[4];
                #pragma unroll
                for (int j = 0; j < 4; j++)
                    hv[j] = __floats2half2_rn(stg[r * 16 + cb + 2 * j],
                                              stg[r * 16 + cb + 2 * j + 1]);
                const int grow = bm0 + wm + mi * 16 + r;
                const int gcol = wn + ni * 16 + cb;
                __half* dst;
                if (hsplit) {                      // head-split [bh, t, d]
                    const int b = grow >> 11, tt = grow & 2047;
                    dst = Cp + ((size_t)((b << 4) + (bn0 >> 7)) * SEQ + tt) * DH + gcol;
                } else {
                    dst = Cp + coff + (size_t)grow * ldc + bn0 + gcol;
                }
                *reinterpret_cast<uint4*>(dst) = *reinterpret_cast<uint4*>(hv);
                __syncwarp();
            }
    }
}

// ------ fused flash attention, q-tile 128 x k-tile 64, occ 2 ------
constexpr int AQP = 136;                       // Q/K pitch (halves)
constexpr int AVP = 72;                        // V pitch (halves)
constexpr int ASP = 68;                        // S pitch (floats)
constexpr int APP = 136;                       // P pitch (halves, overlays S)
constexpr int OFF_K = 128 * AQP * 2;           // 34816 (after Q)
constexpr int OFF_V = OFF_K + 64 * AQP * 2;    // 52224
constexpr int OFF_S = OFF_V + 128 * AVP * 2;   // 70656
constexpr int OFF_R = OFF_S + 128 * ASP * 4;   // 105472
constexpr int SMEM_ATT = OFF_R + 128 * 4;      // 105984

__global__ void __launch_bounds__(256, 2)
attn_fused128(const __half* __restrict__ qh,   // [bh, t, d]
              const __half* __restrict__ kh,   // [bh, s, d] (pre-scaled)
              const __half* __restrict__ vp,   // [bh, d, s]
              float* __restrict__ ctx)         // [b, t, E]
{
    extern __shared__ __align__(128) char smem[];
    __half* Qs = (__half*)smem;
    __half* Ks = (__half*)(smem + OFF_K);
    __half* Vs = (__half*)(smem + OFF_V);
    float*  Ss = (float*)(smem + OFF_S);
    __half* Ps = (__half*)(smem + OFF_S);      // P overlays S (reg-staged, warp-fenced)
    float*  rowsum = (float*)(smem + OFF_R);
    float*  Os = (float*)smem;                 // final O staging overlays Q/K/V

    const int bh = blockIdx.x & 31;
    const int qt = 15 - (blockIdx.x >> 5);     // heavy q-tiles first
    const int b = bh >> 4, h = bh & 15;
    const int tid = threadIdx.x;
    const int wid = tid >> 5;
    const int wm = (wid & 3) * 32;             // QK warp rows (q)
    const int wn = (wid >> 2) * 32;            // QK warp cols (k)
    const int on = (wid >> 2) * 64;            // PV warp cols (d)

    // load Q tile: 128 x 128 halves
    {
        const __half* qg = qh + ((size_t)bh * SEQ + qt * 128) * DH;
        #pragma unroll
        for (int i = 0; i < 8; i++) {
            int s = i * 256 + tid;
            int row = s >> 4, seg = s & 15;
            uint32_t dst = smem_u32(Qs + row * AQP + seg * 8);
            asm volatile("cp.async.cg.shared.global [%0], [%1], 16;"
                         :: "r"(dst), "l"(qg + (size_t)row * DH + seg * 8));
        }
        asm volatile("cp.async.commit_group;" ::: "memory");
    }
    if (tid < 128) rowsum[tid] = 0.0f;

    wmma::fragment<wmma::accumulator, 16, 16, 16, float> oacc[2][4];
    #pragma unroll
    for (int mi = 0; mi < 2; mi++)
        #pragma unroll
        for (int j = 0; j < 4; j++) wmma::fill_fragment(oacc[mi][j], 0.0f);

    const int nkt = 2 * qt + 2;
    for (int kt = 0; kt < nkt; kt++) {
        // load K (64x128) and V (128x64) tiles
        {
            const __half* kg = kh + ((size_t)bh * SEQ + kt * 64) * DH;
            const __half* vg = vp + (size_t)bh * DH * SEQ + kt * 64;
            #pragma unroll
            for (int i = 0; i < 4; i++) {
                int s = i * 256 + tid;
                int rowk = s >> 4, segk = s & 15;
                uint32_t dk = smem_u32(Ks + rowk * AQP + segk * 8);
                asm volatile("cp.async.cg.shared.global [%0], [%1], 16;"
                             :: "r"(dk), "l"(kg + (size_t)rowk * DH + segk * 8));
                int rowv = s >> 3, segv = s & 7;
                uint32_t dv = smem_u32(Vs + rowv * AVP + segv * 8);
                asm volatile("cp.async.cg.shared.global [%0], [%1], 16;"
                             :: "r"(dv), "l"(vg + (size_t)rowv * SEQ + segv * 8));
            }
            asm volatile("cp.async.commit_group;" ::: "memory");
            asm volatile("cp.async.wait_group 0;" ::: "memory");
        }
        __syncthreads();

        // S = Q @ K^T  (128x64), warp tile 32x32
        {
            wmma::fragment<wmma::accumulator, 16, 16, 16, float> sacc[2][2];
            #pragma unroll
            for (int mi = 0; mi < 2; mi++)
                #pragma unroll
                for (int j = 0; j < 2; j++) wmma::fill_fragment(sacc[mi][j], 0.0f);
            #pragma unroll
            for (int kk = 0; kk < 8; kk++) {
                wmma::fragment<wmma::matrix_a, 16, 16, 16, __half, wmma::row_major> af[2];
                #pragma unroll
                for (int mi = 0; mi < 2; mi++)
                    wmma::load_matrix_sync(af[mi], Qs + (wm + mi * 16) * AQP + kk * 16, AQP);
                #pragma unroll
                for (int j = 0; j < 2; j++) {
                    wmma::fragment<wmma::matrix_b, 16, 16, 16, __half, wmma::col_major> bf;
                    wmma::load_matrix_sync(bf, Ks + (wn + j * 16) * AQP + kk * 16, AQP);
                    #pragma unroll
                    for (int mi = 0; mi < 2; mi++)
                        wmma::mma_sync(sacc[mi][j], af[mi], bf, sacc[mi][j]);
                }
            }
            #pragma unroll
            for (int mi = 0; mi < 2; mi++)
                #pragma unroll
                for (int j = 0; j < 2; j++)
                    wmma::store_matrix_sync(Ss + (wm + mi * 16) * ASP + wn + j * 16,
                                            sacc[mi][j], ASP, wmma::mem_row_major);
        }
        __syncthreads();

        // exp (no max-sub) + causal mask; P overlays S: reg-stage, warp fence, write
        {
            const int row = tid >> 1;
            const int c0 = (tid & 1) * 32;
            const bool diag = (kt >= 2 * qt);
            const float* srow = Ss + row * ASP + c0;
            float4 f[8];
            #pragma unroll
            for (int j = 0; j < 8; j++) f[j] = *reinterpret_cast<const float4*>(srow + 4 * j);
            __syncwarp();                        // all reads in warp done before overlay writes
            const int t = qt * 128 + row;
            const int cbase = kt * 64 + c0;
            float part = 0.0f;
            __half hv[32];
            #pragma unroll
            for (int j = 0; j < 8; j++) {
                float e0 = (diag && cbase + 4 * j + 0 > t) ? 0.0f : __expf(f[j].x);
                float e1 = (diag && cbase + 4 * j + 1 > t) ? 0.0f : __expf(f[j].y);
                float e2 = (diag && cbase + 4 * j + 2 > t) ? 0.0f : __expf(f[j].z);
                float e3 = (diag && cbase + 4 * j + 3 > t) ? 0.0f : __expf(f[j].w);
                part += (e0 + e1) + (e2 + e3);
                hv[4 * j + 0] = __float2half_rn(e0);
                hv[4 * j + 1] = __float2half_rn(e1);
                hv[4 * j + 2] = __float2half_rn(e2);
                hv[4 * j + 3] = __float2half_rn(e3);
            }
            __half* prow = Ps + row * APP + c0;
            #pragma unroll
            for (int j = 0; j < 4; j++)
                *reinterpret_cast<uint4*>(prow + 8 * j) = *reinterpret_cast<uint4*>(hv + 8 * j);
            part += __shfl_xor_sync(0xffffffffu, part, 1);
            if ((tid & 1) == 0) rowsum[row] += part;
        }
        __syncthreads();

        // O += P @ V^T  (V stored [d, s]: col_major B with k = s = 64), warp 32x64
        #pragma unroll
        for (int kk = 0; kk < 4; kk++) {
            wmma::fragment<wmma::matrix_a, 16, 16, 16, __half, wmma::row_major> af[2];
            #pragma unroll
            for (int mi = 0; mi < 2; mi++)
                wmma::load_matrix_sync(af[mi], Ps + (wm + mi * 16) * APP + kk * 16, APP);
            #pragma unroll
            for (int j = 0; j < 4; j++) {
                wmma::fragment<wmma::matrix_b, 16, 16, 16, __half, wmma::col_major> bf;
                wmma::load_matrix_sync(bf, Vs + (on + j * 16) * AVP + kk * 16, AVP);
                #pragma unroll
                for (int mi = 0; mi < 2; mi++)
                    wmma::mma_sync(oacc[mi][j], af[mi], bf, oacc[mi][j]);
            }
        }
        __syncthreads();   // all P/V reads done before next iter's loads/stores
    }

    // stage O (128x128 fp32, pitch 132) over Q/K/V smem, normalize, write ctx
    #pragma unroll
    for (int mi = 0; mi < 2; mi++)
        #pragma unroll
        for (int j = 0; j < 4; j++)
            wmma::store_matrix_sync(Os + (wm + mi * 16) * 132 + on + j * 16,
                                    oacc[mi][j], 132, wmma::mem_row_major);
    __syncthreads();
    {
        const int row = tid >> 1;
        const int c0 = (tid & 1) * 64;
        const float inv = 1.0f / rowsum[row];
        const int t = qt * 128 + row;
        float* dst = ctx + ((size_t)(b * SEQ + t)) * EMB + h * DH + c0;
        const float* srow = Os + row * 132 + c0;
        #pragma unroll
        for (int c = 0; c < 64; c += 4) {
            float4 v;
            v.x = srow[c] * inv; v.y = srow[c + 1] * inv;
            v.z = srow[c + 2] * inv; v.w = srow[c + 3] * inv;
            *reinterpret_cast<float4*>(dst + c) = v;
        }
    }
}

// ---------------- block reductions ----------------
__device__ __forceinline__ float blk_sum(float v) {
    __shared__ float sh_s[32];
    __shared__ float tot_s;
    int lane = threadIdx.x & 31, w = threadIdx.x >> 5;
    #pragma unroll
    for (int o = 16; o; o >>= 1) v += __shfl_xor_sync(0xffffffffu, v, o);
    if (lane == 0) sh_s[w] = v;
    __syncthreads();
    if (threadIdx.x == 0) {
        float r = 0.f; int nw = blockDim.x >> 5;
        for (int i = 0; i < nw; i++) r += sh_s[i];
        tot_s = r;
    }
    __syncthreads();
    float r = tot_s;
    __syncthreads();
    return r;
}

// ---------------- conversions / repack / norms ----------------
__global__ void f2h_k(const float* __restrict__ in, __half* __restrict__ out) {
    int i = (blockIdx.x * blockDim.x + threadIdx.x) * 4;
    float4 v = *reinterpret_cast<const float4*>(in + i);
    __half2 h[2];
    h[0] = __floats2half2_rn(v.x, v.y);
    h[1] = __floats2half2_rn(v.z, v.w);
    *reinterpret_cast<uint2*>(out + i) = *reinterpret_cast<uint2*>(h);
}

struct W7 { const float* p[7]; };
__global__ void f2h7_k(W7 ws, __half* __restrict__ out) {
    const int plane = blockIdx.y;
    const float* in = ws.p[plane];
    __half* o = out + (size_t)plane * EMB * EMB;
    int i = (blockIdx.x * blockDim.x + threadIdx.x) * 4;
    float4 v = *reinterpret_cast<const float4*>(in + i);
    __half2 h[2];
    h[0] = __floats2half2_rn(v.x, v.y);
    h[1] = __floats2half2_rn(v.z, v.w);
    *reinterpret_cast<uint2*>(o + i) = *reinterpret_cast<uint2*>(h);
}

// smem-transpose repack: v[b, s, d*16+h] -> vp[(b*16+h)*128 + d, s]
__global__ void __launch_bounds__(256)
repack_v_t(const __half* __restrict__ src, __half* __restrict__ dst) {
    __shared__ __half Ts[64][136];
    const int eblk = blockIdx.x;    // 0..15 (128 e-cols each)
    const int sblk = blockIdx.y;    // 0..31 (64 s-rows each)
    const int b    = blockIdx.z;    // 0..1
    const int tid = threadIdx.x;

    const __half* sp = src + ((size_t)(b * SEQ + sblk * 64)) * EMB + eblk * 128;
    #pragma unroll
    for (int i = 0; i < 4; i++) {
        int idx = i * 256 + tid;
        int row = idx >> 4, seg = idx & 15;
        *reinterpret_cast<uint4*>(&Ts[row][seg * 8]) =
            *reinterpret_cast<const uint4*>(sp + (size_t)row * EMB + seg * 8);
    }
    __syncthreads();

    const int L  = tid >> 1;        // local e index 0..127
    const int sh = tid & 1;         // s half (32 each)
    const int d = eblk * 8 + (L >> 4);
    const int h = L & 15;
    __half buf[32];
    #pragma unroll
    for (int i = 0; i < 32; i++) buf[i] = Ts[sh * 32 + i][L];
    __half* dp = dst + ((size_t)(b * 16 + h) * 128 + d) * SEQ + sblk * 64 + sh * 32;
    #pragma unroll
    for (int i = 0; i < 4; i++)
        *reinterpret_cast<uint4*>(dp + i * 8) = *reinterpret_cast<uint4*>(&buf[i * 8]);
}

__global__ void layernorm_h(const float* __restrict__ in, __half* __restrict__ out,
                            const float* __restrict__ g, const float* __restrict__ b) {
    const float* row = in + (size_t)blockIdx.x * EMB;
    __half* orow = out + (size_t)blockIdx.x * EMB;
    __shared__ float buf[EMB];
    float s = 0.f;
    for (int i = threadIdx.x; i < EMB; i += blockDim.x) { float v = row[i]; buf[i] = v; s += v; }
    const float mu = blk_sum(s) * (1.0f / EMB);
    float sq = 0.f;
    for (int i = threadIdx.x; i < EMB; i += blockDim.x) { float d = buf[i] - mu; sq += d * d; }
    const float var = blk_sum(sq) * (1.0f / EMB);
    const float inv = rsqrtf(var + 1e-5f);
    for (int i = threadIdx.x; i < EMB; i += blockDim.x)
        orow[i] = __float2half_rn((buf[i] - mu) * inv * g[i] + b[i]);
}

// x := rmsnorm(x) (fp32, residual base) and xh := half(x)
__global__ void rmsnorm_dual(float* __restrict__ x, __half* __restrict__ xh,
                             const float* __restrict__ g) {
    float* row = x + (size_t)blockIdx.x * EMB;
    __half* orow = xh + (size_t)blockIdx.x * EMB;
    __shared__ float buf[EMB];
    float ss = 0.f;
    for (int i = threadIdx.x; i < EMB; i += blockDim.x) { float v = row[i]; buf[i] = v; ss += v * v; }
    ss = blk_sum(ss);
    const float sc = rsqrtf(ss * (1.0f / EMB) + 1e-6f);
    for (int i = threadIdx.x; i < EMB; i += blockDim.x) {
        float r = g[i] * buf[i] * sc;
        row[i] = r;
        orow[i] = __float2half_rn(r);
    }
}

// out = x2 + mlp_rms_g * g * rsqrt(mean(g^2)+eps),  g = w*sigmoid(beta*w)*u  (half w,u)
__global__ void final_k(const float* __restrict__ x2, const __half* __restrict__ wv,
                        const __half* __restrict__ uv, const float* __restrict__ beta,
                        const float* __restrict__ gamma, float* __restrict__ out) {
    const size_t r = blockIdx.x;
    const float bet = beta[0];
    const __half* wrow = wv + r * EMB;
    const __half* urow = uv + r * EMB;
    __shared__ float buf[EMB];
    float ss = 0.f;
    for (int i = threadIdx.x; i < EMB; i += blockDim.x) {
        float wq = __half2float(wrow[i]);
        float s = 1.0f / (1.0f + __expf(-bet * wq));
        float gq = wq * s * __half2float(urow[i]);
        buf[i] = gq; ss += gq * gq;
    }
    ss = blk_sum(ss);
    const float sc = rsqrtf(ss * (1.0f / EMB) + 1e-6f);
    for (int i = threadIdx.x; i < EMB; i += blockDim.x)
        out[r * EMB + i] = x2[r * EMB + i] + gamma[i] * buf[i] * sc;
}

// ---------------- launcher ----------------
extern "C" void kernel_launch(void* const* d_in, const int* in_sizes, int n_in,
                              void* d_out, int out_size) {
    const float* x     = (const float*)d_in[0];
    const float* Wq    = (const float*)d_in[1];
    const float* Wk    = (const float*)d_in[2];
    const float* Wv    = (const float*)d_in[3];
    const float* Wo    = (const float*)d_in[4];
    const float* ln_g  = (const float*)d_in[5];
    const float* ln_b  = (const float*)d_in[6];
    const float* rms_g = (const float*)d_in[7];
    const float* W0    = (const float*)d_in[8];
    const float* swW   = (const float*)d_in[9];
    const float* swV   = (const float*)d_in[10];
    const float* swb   = (const float*)d_in[11];
    const float* mrg   = (const float*)d_in[12];
    float* out = (float*)d_out;

    __half *xh, *wh, *qkv, *vp, *cth, *x2h, *hh, *wuh;
    float *ctx, *xa;
    cudaGetSymbolAddress((void**)&xh,  g_xh);
    cudaGetSymbolAddress((void**)&wh,  g_wh);
    cudaGetSymbolAddress((void**)&qkv, g_qkvh);
    cudaGetSymbolAddress((void**)&vp,  g_vp);
    cudaGetSymbolAddress((void**)&ctx, g_ctx);
    cudaGetSymbolAddress((void**)&cth, g_cth);
    cudaGetSymbolAddress((void**)&xa,  g_xa);
    cudaGetSymbolAddress((void**)&x2h, g_x2h);
    cudaGetSymbolAddress((void**)&hh,  g_hh);
    cudaGetSymbolAddress((void**)&wuh, g_wuh);

    __half* qh = qkv + 0 * PLANE;
    __half* kh = qkv + 1 * PLANE;
    __half* v  = qkv + 2 * PLANE;
    __half* wvh = wuh + 0 * PLANE;
    __half* uvh = wuh + 1 * PLANE;
    const long long NW = (long long)EMB * EMB;

    cudaFuncSetAttribute(gemm_h<2,false>, cudaFuncAttributeMaxDynamicSharedMemorySize, SMEM_GEMM);
    cudaFuncSetAttribute(gemm_h<0,true >, cudaFuncAttributeMaxDynamicSharedMemorySize, SMEM_GEMM);
    cudaFuncSetAttribute(gemm_h<1,false>, cudaFuncAttributeMaxDynamicSharedMemorySize, SMEM_GEMM);
    cudaFuncSetAttribute(attn_fused128,   cudaFuncAttributeMaxDynamicSharedMemorySize, SMEM_ATT);

    const float scale = 0.08838834764831845f;  // 1/sqrt(128)
    const int NEW = MTOT * EMB;                // 8,388,608
    dim3 gblk(128);                            // 4-warp GEMM CTAs
    dim3 blk(256);

    // fp32 -> fp16 operand conversions
    f2h_k<<<NEW / 1024, 256>>>(x, xh);
    W7 ws; ws.p[0]=Wq; ws.p[1]=Wk; ws.p[2]=Wv; ws.p[3]=Wo; ws.p[4]=W0; ws.p[5]=swW; ws.p[6]=swV;
    f2h7_k<<<dim3(NW / 1024, 7), 256>>>(ws, wh);

    // merged QKV projection: z selects weight plane + output plane
    dim3 gqkv(EMB / BN, MTOT / BM, 3);         // (16,32,3)
    gemm_h<2,false><<<gqkv, gblk, SMEM_GEMM>>>(64,
        xh, EMB, 0, wh, EMB, EMB, nullptr, qkv, EMB, nullptr, 1.0f, scale, 0);

    repack_v_t<<<dim3(16, 32, 2), 256>>>(v, vp);

    // fused attention: QK^T + causal softmax + PV -> ctx fp32 (128x64 tiles)
    attn_fused128<<<512, blk, SMEM_ATT>>>(qh, kh, vp, ctx);

    layernorm_h<<<MTOT, 256>>>(ctx, cth, ln_g, ln_b);

    // xa = x + cth @ Wo^T (fp32, residual fused via accumulator init)
    dim3 gp(EMB / BN, MTOT / BM, 1);           // (16,32,1)
    gemm_h<0,true><<<gp, gblk, SMEM_GEMM>>>(64,
        cth, EMB, 0, wh + 3 * NW, EMB, 0, xa, nullptr, EMB, x, 1.0f, 1.0f, 0);

    rmsnorm_dual<<<MTOT, 256>>>(xa, x2h, rms_g);

    // h = x2 @ W0^T (half out)
    gemm_h<1,false><<<gp, gblk, SMEM_GEMM>>>(64,
        x2h, EMB, 0, wh + 4 * NW, EMB, 0, nullptr, hh, EMB, nullptr, 1.0f, 1.0f, 0);

    // merged swW/swV: z selects weight plane + half output plane
    dim3 gsw(EMB / BN, MTOT / BM, 2);          // (16,32,2)
    gemm_h<1,false><<<gsw, gblk, SMEM_GEMM>>>(64,
        hh, EMB, 0, wh + 5 * NW, EMB, EMB, nullptr, wuh, EMB, nullptr, 1.0f, 1.0f,
        (long long)PLANE);

    final_k<<<MTOT, 256>>>(xa, wvh, uvh, swb, mrg, out);   // swiglu + rmsnorm + residual
}

// round 11
// speedup vs baseline: 1.0689x; 1.0689x over previous
#include <cuda_runtime.h>
#include <cuda_fp16.h>
#include <mma.h>
#include <cstdint>

using namespace nvcuda;

#define SEQ 2048
#define EMB 2048
#define NB  2
#define NH  16
#define DH  128
#define MTOT (NB*SEQ)   // 4096
#define PLANE ((size_t)MTOT*EMB)

// ---------------- scratch (static device globals) ----------------
__device__ __half g_xh  [MTOT*EMB];
__device__ __half g_wh  [7][EMB*EMB];       // wq,wk,wv,wo,w0,sww,swv (contiguous)
__device__ __half g_qkvh[3][MTOT*EMB];      // plane0: qh [bh,t,d]; 1: kh [bh,s,d]; 2: v [b,s,E]
__device__ __half g_vp  [MTOT*EMB];         // [bh, d, s]
__device__ float  g_ctx [MTOT*EMB];
__device__ __half g_cth [MTOT*EMB];
__device__ float  g_xa  [MTOT*EMB];
__device__ __half g_x2h [MTOT*EMB];
__device__ __half g_hh  [MTOT*EMB];
__device__ __half g_wuh [2][MTOT*EMB];      // plane0: w, plane1: u (fp16)

__device__ __forceinline__ uint32_t smem_u32(const void* p) {
    uint32_t a;
    asm("{ .reg .u64 t; cvta.to.shared.u64 t, %1; cvt.u32.u64 %0, t; }" : "=r"(a) : "l"(p));
    return a;
}

// ---------------- fp16 wmma NT GEMM, 3-stage cp.async (R9 config) ----------
constexpr int BM = 128, BN = 128, PITCH = 40;          // pitch in halves
constexpr int STG_BYTES   = BM * PITCH * 2;            // 10240 per operand
constexpr int STAGE_BYTES = 2 * STG_BYTES;             // 20480 (A+B)
constexpr int NSTG = 3;
constexpr int SMEM_GEMM   = NSTG * STAGE_BYTES;        // 61440

// OMODE: 0 = fp32 out (opt RES); 1 = half plain out; 2 = QKV combined (3 planes)
template<int OMODE, bool RES>
__global__ void __launch_bounds__(256, 2)
gemm_h(int nk,
       const __half* __restrict__ A, int lda, int zRowA,
       const __half* __restrict__ B, int ldb, int zRowB,
       float* __restrict__ C, __half* __restrict__ Ch, int ldc,
       const float* __restrict__ Rres, float alphaA, float alphaB,
       long long sC)
{
    const int bn0 = blockIdx.x * BN;
    const int bm0 = blockIdx.y * BM;
    const int z = blockIdx.z;

    extern __shared__ __align__(128) char smem[];
    const int tid  = threadIdx.x;
    const int wid  = tid >> 5;
    const int lane = tid & 31;
    const int wm = (wid & 3) * 32;
    const int wn = (wid >> 2) * 64;

    const __half* Abase = A + (size_t)(z * zRowA + bm0) * lda;
    const __half* Bbase = B + (size_t)(z * zRowB + bn0) * ldb;
    const long long coff = (long long)z * sC;

    auto load_chunk = [&](int kc) {
        const int st = kc % NSTG;
        char* sA = smem + st * STAGE_BYTES;
        char* sB = sA + STG_BYTES;
        const __half* ag = Abase + kc * 32;
        const __half* bg = Bbase + kc * 32;
        #pragma unroll
        for (int i = 0; i < 2; i++) {            // 512 16B segs per operand
            int idx = i * 256 + tid;
            int row = idx >> 2, seg = idx & 3;
            uint32_t da = smem_u32(sA + row * (PITCH * 2) + seg * 16);
            const __half* srca = ag + (size_t)row * lda + seg * 8;
            asm volatile("cp.async.cg.shared.global [%0], [%1], 16;" :: "r"(da), "l"(srca));
            uint32_t db = smem_u32(sB + row * (PITCH * 2) + seg * 16);
            const __half* srcb = bg + (size_t)row * ldb + seg * 8;
            asm volatile("cp.async.cg.shared.global [%0], [%1], 16;" :: "r"(db), "l"(srcb));
        }
        asm volatile("cp.async.commit_group;" ::: "memory");
    };

    wmma::fragment<wmma::accumulator, 16, 16, 16, float> acc[2][4];
    #pragma unroll
    for (int mi = 0; mi < 2; mi++)
        #pragma unroll
        for (int ni = 0; ni < 4; ni++) {
            if (RES)
                wmma::load_matrix_sync(acc[mi][ni],
                    Rres + coff + (long long)(bm0 + wm + mi * 16) * ldc + (bn0 + wn + ni * 16),
                    ldc, wmma::mem_row_major);
            else
                wmma::fill_fragment(acc[mi][ni], 0.0f);
        }

    load_chunk(0);
    if (nk > 1) load_chunk(1);

    for (int kc = 0; kc < nk; kc++) {
        if (kc + 1 < nk)
            asm volatile("cp.async.wait_group 1;" ::: "memory");
        else
            asm volatile("cp.async.wait_group 0;" ::: "memory");
        __syncthreads();                          // single sync per chunk
        if (kc + 2 < nk) load_chunk(kc + 2);

        const __half* sA = (const __half*)(smem + (kc % NSTG) * STAGE_BYTES);
        const __half* sB = sA + BM * PITCH;
        #pragma unroll
        for (int kk = 0; kk < 2; kk++) {
            wmma::fragment<wmma::matrix_a, 16, 16, 16, __half, wmma::row_major> af[2];
            #pragma unroll
            for (int mi = 0; mi < 2; mi++)
                wmma::load_matrix_sync(af[mi], sA + (wm + mi * 16) * PITCH + kk * 16, PITCH);
            #pragma unroll
            for (int nh = 0; nh < 2; nh++) {
                wmma::fragment<wmma::matrix_b, 16, 16, 16, __half, wmma::col_major> bf[2];
                #pragma unroll
                for (int j = 0; j < 2; j++)
                    wmma::load_matrix_sync(bf[j], sB + (wn + (nh * 2 + j) * 16) * PITCH + kk * 16, PITCH);
                #pragma unroll
                for (int mi = 0; mi < 2; mi++)
                    #pragma unroll
                    for (int j = 0; j < 2; j++)
                        wmma::mma_sync(acc[mi][nh * 2 + j], af[mi], bf[j], acc[mi][nh * 2 + j]);
            }
        }
    }

    const float alpha = (OMODE == 2) ? ((z == 1) ? alphaB : alphaA) : alphaA;
    if (alpha != 1.0f) {
        #pragma unroll
        for (int mi = 0; mi < 2; mi++)
            #pragma unroll
            for (int ni = 0; ni < 4; ni++)
                #pragma unroll
                for (int e = 0; e < acc[mi][ni].num_elements; e++)
                    acc[mi][ni].x[e] *= alpha;
    }

    if (OMODE == 0) {
        float* Cp = C + coff;
        #pragma unroll
        for (int mi = 0; mi < 2; mi++)
            #pragma unroll
            for (int ni = 0; ni < 4; ni++)
                wmma::store_matrix_sync(
                    Cp + (long long)(bm0 + wm + mi * 16) * ldc + (bn0 + wn + ni * 16),
                    acc[mi][ni], ldc, wmma::mem_row_major);
    } else {
        __syncthreads();                          // all MMAs done before smem reuse
        float* stg = (float*)smem + wid * 256;
        __half* Cp = (OMODE == 2) ? (Ch + (size_t)z * PLANE) : Ch;
        const bool hsplit = (OMODE == 2) && (z < 2);
        #pragma unroll
        for (int mi = 0; mi < 2; mi++)
            #pragma unroll
            for (int ni = 0; ni < 4; ni++) {
                wmma::store_matrix_sync(stg, acc[mi][ni], 16, wmma::mem_row_major);
                __syncwarp();
                const int r  = lane >> 1;
                const int cb = (lane & 1) * 8;
                __half2 hv[4];
                #pragma unroll
                for (int j = 0; j < 4; j++)
                    hv[j] = __floats2half2_rn(stg[r * 16 + cb + 2 * j],
                                              stg[r * 16 + cb + 2 * j + 1]);
                const int grow = bm0 + wm + mi * 16 + r;
                const int gcol = wn + ni * 16 + cb;
                __half* dst;
                if (hsplit) {                      // head-split [bh, t, d]
                    const int b = grow >> 11, tt = grow & 2047;
                    dst = Cp + ((size_t)((b << 4) + (bn0 >> 7)) * SEQ + tt) * DH + gcol;
                } else {
                    dst = Cp + coff + (size_t)grow * ldc + bn0 + gcol;
                }
                *reinterpret_cast<uint4*>(dst) = *reinterpret_cast<uint4*>(hv);
                __syncwarp();
            }
    }
}

// ------ fused flash attention, q-tile 128 x k-tile 64, occ 2 ------
// K and V prefetched in SEPARATE cp.async groups: K(kt+1) issued once QK(kt)
// is done reading Ks; V(kt+1) issued once PV(kt) is done reading Vs. Each
// wait_group 1 gates only the group actually needed next.
constexpr int AQP = 136;                       // Q/K pitch (halves)
constexpr int AVP = 72;                        // V pitch (halves)
constexpr int ASP = 68;                        // S pitch (floats)
constexpr int APP = 136;                       // P pitch (halves, overlays S)
constexpr int OFF_K = 128 * AQP * 2;           // 34816 (after Q)
constexpr int OFF_V = OFF_K + 64 * AQP * 2;    // 52224
constexpr int OFF_S = OFF_V + 128 * AVP * 2;   // 70656
constexpr int OFF_R = OFF_S + 128 * ASP * 4;   // 105472
constexpr int SMEM_ATT = OFF_R + 128 * 4;      // 105984

__global__ void __launch_bounds__(256, 2)
attn_fused128(const __half* __restrict__ qh,   // [bh, t, d]
              const __half* __restrict__ kh,   // [bh, s, d] (pre-scaled)
              const __half* __restrict__ vp,   // [bh, d, s]
              float* __restrict__ ctx)         // [b, t, E]
{
    extern __shared__ __align__(128) char smem[];
    __half* Qs = (__half*)smem;
    __half* Ks = (__half*)(smem + OFF_K);
    __half* Vs = (__half*)(smem + OFF_V);
    float*  Ss = (float*)(smem + OFF_S);
    __half* Ps = (__half*)(smem + OFF_S);      // P overlays S (reg-staged, warp-fenced)
    float*  rowsum = (float*)(smem + OFF_R);
    float*  Os = (float*)smem;                 // final O staging overlays Q/K/V

    const int bh = blockIdx.x & 31;
    const int qt = 15 - (blockIdx.x >> 5);     // heavy q-tiles first
    const int b = bh >> 4, h = bh & 15;
    const int tid = threadIdx.x;
    const int wid = tid >> 5;
    const int wm = (wid & 3) * 32;             // QK warp rows (q)
    const int wn = (wid >> 2) * 32;            // QK warp cols (k)
    const int on = (wid >> 2) * 64;            // PV warp cols (d)

    const int nkt = 2 * qt + 2;

    // K tile load (no commit) — 64 x 128 halves
    auto load_k_body = [&](int kt) {
        const __half* kg = kh + ((size_t)bh * SEQ + kt * 64) * DH;
        #pragma unroll
        for (int i = 0; i < 4; i++) {
            int s = i * 256 + tid;
            int row = s >> 4, seg = s & 15;
            uint32_t dk = smem_u32(Ks + row * AQP + seg * 8);
            asm volatile("cp.async.cg.shared.global [%0], [%1], 16;"
                         :: "r"(dk), "l"(kg + (size_t)row * DH + seg * 8));
        }
    };
    // V tile load (no commit) — 128 x 64 halves
    auto load_v_body = [&](int kt) {
        const __half* vg = vp + (size_t)bh * DH * SEQ + kt * 64;
        #pragma unroll
        for (int i = 0; i < 4; i++) {
            int s = i * 256 + tid;
            int row = s >> 3, seg = s & 7;
            uint32_t dv = smem_u32(Vs + row * AVP + seg * 8);
            asm volatile("cp.async.cg.shared.global [%0], [%1], 16;"
                         :: "r"(dv), "l"(vg + (size_t)row * SEQ + seg * 8));
        }
    };

    // prologue group 1: Q tile + K(0)
    {
        const __half* qg = qh + ((size_t)bh * SEQ + qt * 128) * DH;
        #pragma unroll
        for (int i = 0; i < 8; i++) {
            int s = i * 256 + tid;
            int row = s >> 4, seg = s & 15;
            uint32_t dst = smem_u32(Qs + row * AQP + seg * 8);
            asm volatile("cp.async.cg.shared.global [%0], [%1], 16;"
                         :: "r"(dst), "l"(qg + (size_t)row * DH + seg * 8));
        }
        load_k_body(0);
        asm volatile("cp.async.commit_group;" ::: "memory");
    }
    // prologue group 2: V(0)
    load_v_body(0);
    asm volatile("cp.async.commit_group;" ::: "memory");

    if (tid < 128) rowsum[tid] = 0.0f;

    wmma::fragment<wmma::accumulator, 16, 16, 16, float> oacc[2][4];
    #pragma unroll
    for (int mi = 0; mi < 2; mi++)
        #pragma unroll
        for (int j = 0; j < 4; j++) wmma::fill_fragment(oacc[mi][j], 0.0f);

    // steady-state pending groups at loop top: { K(kt)[+Q], V(kt) } -> wait_group 1 = K ready
    for (int kt = 0; kt < nkt; kt++) {
        asm volatile("cp.async.wait_group 1;" ::: "memory");   // K(kt) (+Q) arrived
        __syncthreads();

        // S = Q @ K^T  (128x64), warp tile 32x32
        {
            wmma::fragment<wmma::accumulator, 16, 16, 16, float> sacc[2][2];
            #pragma unroll
            for (int mi = 0; mi < 2; mi++)
                #pragma unroll
                for (int j = 0; j < 2; j++) wmma::fill_fragment(sacc[mi][j], 0.0f);
            #pragma unroll
            for (int kk = 0; kk < 8; kk++) {
                wmma::fragment<wmma::matrix_a, 16, 16, 16, __half, wmma::row_major> af[2];
                #pragma unroll
                for (int mi = 0; mi < 2; mi++)
                    wmma::load_matrix_sync(af[mi], Qs + (wm + mi * 16) * AQP + kk * 16, AQP);
                #pragma unroll
                for (int j = 0; j < 2; j++) {
                    wmma::fragment<wmma::matrix_b, 16, 16, 16, __half, wmma::col_major> bf;
                    wmma::load_matrix_sync(bf, Ks + (wn + j * 16) * AQP + kk * 16, AQP);
                    #pragma unroll
                    for (int mi = 0; mi < 2; mi++)
                        wmma::mma_sync(sacc[mi][j], af[mi], bf, sacc[mi][j]);
                }
            }
            #pragma unroll
            for (int mi = 0; mi < 2; mi++)
                #pragma unroll
                for (int j = 0; j < 2; j++)
                    wmma::store_matrix_sync(Ss + (wm + mi * 16) * ASP + wn + j * 16,
                                            sacc[mi][j], ASP, wmma::mem_row_major);
        }
        __syncthreads();                          // QK done: Ks reusable, S visible

        // prefetch K(kt+1) — empty commit keeps group bookkeeping uniform
        if (kt + 1 < nkt) load_k_body(kt + 1);
        asm volatile("cp.async.commit_group;" ::: "memory");

        // exp (no max-sub) + causal mask; P overlays S: reg-stage, warp fence, write
        {
            const int row = tid >> 1;
            const int c0 = (tid & 1) * 32;
            const bool diag = (kt >= 2 * qt);
            const float* srow = Ss + row * ASP + c0;
            float4 f[8];
            #pragma unroll
            for (int j = 0; j < 8; j++) f[j] = *reinterpret_cast<const float4*>(srow + 4 * j);
            __syncwarp();                        // all reads in warp done before overlay writes
            const int t = qt * 128 + row;
            const int cbase = kt * 64 + c0;
            float part = 0.0f;
            __half hv[32];
            #pragma unroll
            for (int j = 0; j < 8; j++) {
                float e0 = (diag && cbase + 4 * j + 0 > t) ? 0.0f : __expf(f[j].x);
                float e1 = (diag && cbase + 4 * j + 1 > t) ? 0.0f : __expf(f[j].y);
                float e2 = (diag && cbase + 4 * j + 2 > t) ? 0.0f : __expf(f[j].z);
                float e3 = (diag && cbase + 4 * j + 3 > t) ? 0.0f : __expf(f[j].w);
                part += (e0 + e1) + (e2 + e3);
                hv[4 * j + 0] = __float2half_rn(e0);
                hv[4 * j + 1] = __float2half_rn(e1);
                hv[4 * j + 2] = __float2half_rn(e2);
                hv[4 * j + 3] = __float2half_rn(e3);
            }
            __half* prow = Ps + row * APP + c0;
            #pragma unroll
            for (int j = 0; j < 4; j++)
                *reinterpret_cast<uint4*>(prow + 8 * j) = *reinterpret_cast<uint4*>(hv + 8 * j);
            part += __shfl_xor_sync(0xffffffffu, part, 1);
            if ((tid & 1) == 0) rowsum[row] += part;
        }

        asm volatile("cp.async.wait_group 1;" ::: "memory");   // V(kt) arrived (K(kt+1) may fly)
        __syncthreads();                          // P visible + V visible

        // O += P @ V^T  (V stored [d, s]: col_major B with k = s = 64), warp 32x64
        #pragma unroll
        for (int kk = 0; kk < 4; kk++) {
            wmma::fragment<wmma::matrix_a, 16, 16, 16, __half, wmma::row_major> af[2];
            #pragma unroll
            for (int mi = 0; mi < 2; mi++)
                wmma::load_matrix_sync(af[mi], Ps + (wm + mi * 16) * APP + kk * 16, APP);
            #pragma unroll
            for (int j = 0; j < 4; j++) {
                wmma::fragment<wmma::matrix_b, 16, 16, 16, __half, wmma::col_major> bf;
                wmma::load_matrix_sync(bf, Vs + (on + j * 16) * AVP + kk * 16, AVP);
                #pragma unroll
                for (int mi = 0; mi < 2; mi++)
                    wmma::mma_sync(oacc[mi][j], af[mi], bf, oacc[mi][j]);
            }
        }
        __syncthreads();                          // PV done: Vs reusable, Ps reusable

        // prefetch V(kt+1)
        if (kt + 1 < nkt) load_v_body(kt + 1);
        asm volatile("cp.async.commit_group;" ::: "memory");
    }

    // trailing groups are empty (no writes) — safe to overlay O now.
    // stage O (128x128 fp32, pitch 132) over Q/K/V smem, normalize, write ctx
    #pragma unroll
    for (int mi = 0; mi < 2; mi++)
        #pragma unroll
        for (int j = 0; j < 4; j++)
            wmma::store_matrix_sync(Os + (wm + mi * 16) * 132 + on + j * 16,
                                    oacc[mi][j], 132, wmma::mem_row_major);
    __syncthreads();
    {
        const int row = tid >> 1;
        const int c0 = (tid & 1) * 64;
        const float inv = 1.0f / rowsum[row];
        const int t = qt * 128 + row;
        float* dst = ctx + ((size_t)(b * SEQ + t)) * EMB + h * DH + c0;
        const float* srow = Os + row * 132 + c0;
        #pragma unroll
        for (int c = 0; c < 64; c += 4) {
            float4 v;
            v.x = srow[c] * inv; v.y = srow[c + 1] * inv;
            v.z = srow[c + 2] * inv; v.w = srow[c + 3] * inv;
            *reinterpret_cast<float4*>(dst + c) = v;
        }
    }
}

// ---------------- block reductions ----------------
__device__ __forceinline__ float blk_sum(float v) {
    __shared__ float sh_s[32];
    __shared__ float tot_s;
    int lane = threadIdx.x & 31, w = threadIdx.x >> 5;
    #pragma unroll
    for (int o = 16; o; o >>= 1) v += __shfl_xor_sync(0xffffffffu, v, o);
    if (lane == 0) sh_s[w] = v;
    __syncthreads();
    if (threadIdx.x == 0) {
        float r = 0.f; int nw = blockDim.x >> 5;
        for (int i = 0; i < nw; i++) r += sh_s[i];
        tot_s = r;
    }
    __syncthreads();
    float r = tot_s;
    __syncthreads();
    return r;
}

// ---------------- conversions / repack / norms ----------------
__global__ void f2h_k(const float* __restrict__ in, __half* __restrict__ out) {
    int i = (blockIdx.x * blockDim.x + threadIdx.x) * 4;
    float4 v = *reinterpret_cast<const float4*>(in + i);
    __half2 h[2];
    h[0] = __floats2half2_rn(v.x, v.y);
    h[1] = __floats2half2_rn(v.z, v.w);
    *reinterpret_cast<uint2*>(out + i) = *reinterpret_cast<uint2*>(h);
}

struct W7 { const float* p[7]; };
__global__ void f2h7_k(W7 ws, __half* __restrict__ out) {
    const int plane = blockIdx.y;
    const float* in = ws.p[plane];
    __half* o = out + (size_t)plane * EMB * EMB;
    int i = (blockIdx.x * blockDim.x + threadIdx.x) * 4;
    float4 v = *reinterpret_cast<const float4*>(in + i);
    __half2 h[2];
    h[0] = __floats2half2_rn(v.x, v.y);
    h[1] = __floats2half2_rn(v.z, v.w);
    *reinterpret_cast<uint2*>(o + i) = *reinterpret_cast<uint2*>(h);
}

// smem-transpose repack: v[b, s, d*16+h] -> vp[(b*16+h)*128 + d, s]
__global__ void __launch_bounds__(256)
repack_v_t(const __half* __restrict__ src, __half* __restrict__ dst) {
    __shared__ __half Ts[64][136];
    const int eblk = blockIdx.x;    // 0..15 (128 e-cols each)
    const int sblk = blockIdx.y;    // 0..31 (64 s-rows each)
    const int b    = blockIdx.z;    // 0..1
    const int tid = threadIdx.x;

    const __half* sp = src + ((size_t)(b * SEQ + sblk * 64)) * EMB + eblk * 128;
    #pragma unroll
    for (int i = 0; i < 4; i++) {
        int idx = i * 256 + tid;
        int row = idx >> 4, seg = idx & 15;
        *reinterpret_cast<uint4*>(&Ts[row][seg * 8]) =
            *reinterpret_cast<const uint4*>(sp + (size_t)row * EMB + seg * 8);
    }
    __syncthreads();

    const int L  = tid >> 1;        // local e index 0..127
    const int sh = tid & 1;         // s half (32 each)
    const int d = eblk * 8 + (L >> 4);
    const int h = L & 15;
    __half buf[32];
    #pragma unroll
    for (int i = 0; i < 32; i++) buf[i] = Ts[sh * 32 + i][L];
    __half* dp = dst + ((size_t)(b * 16 + h) * 128 + d) * SEQ + sblk * 64 + sh * 32;
    #pragma unroll
    for (int i = 0; i < 4; i++)
        *reinterpret_cast<uint4*>(dp + i * 8) = *reinterpret_cast<uint4*>(&buf[i * 8]);
}

__global__ void layernorm_h(const float* __restrict__ in, __half* __restrict__ out,
                            const float* __restrict__ g, const float* __restrict__ b) {
    const float* row = in + (size_t)blockIdx.x * EMB;
    __half* orow = out + (size_t)blockIdx.x * EMB;
    __shared__ float buf[EMB];
    float s = 0.f;
    for (int i = threadIdx.x; i < EMB; i += blockDim.x) { float v = row[i]; buf[i] = v; s += v; }
    const float mu = blk_sum(s) * (1.0f / EMB);
    float sq = 0.f;
    for (int i = threadIdx.x; i < EMB; i += blockDim.x) { float d = buf[i] - mu; sq += d * d; }
    const float var = blk_sum(sq) * (1.0f / EMB);
    const float inv = rsqrtf(var + 1e-5f);
    for (int i = threadIdx.x; i < EMB; i += blockDim.x)
        orow[i] = __float2half_rn((buf[i] - mu) * inv * g[i] + b[i]);
}

// x := rmsnorm(x) (fp32, residual base) and xh := half(x)
__global__ void rmsnorm_dual(float* __restrict__ x, __half* __restrict__ xh,
                             const float* __restrict__ g) {
    float* row = x + (size_t)blockIdx.x * EMB;
    __half* orow = xh + (size_t)blockIdx.x * EMB;
    __shared__ float buf[EMB];
    float ss = 0.f;
    for (int i = threadIdx.x; i < EMB; i += blockDim.x) { float v = row[i]; buf[i] = v; ss += v * v; }
    ss = blk_sum(ss);
    const float sc = rsqrtf(ss * (1.0f / EMB) + 1e-6f);
    for (int i = threadIdx.x; i < EMB; i += blockDim.x) {
        float r = g[i] * buf[i] * sc;
        row[i] = r;
        orow[i] = __float2half_rn(r);
    }
}

// out = x2 + mlp_rms_g * g * rsqrt(mean(g^2)+eps),  g = w*sigmoid(beta*w)*u  (half w,u)
__global__ void final_k(const float* __restrict__ x2, const __half* __restrict__ wv,
                        const __half* __restrict__ uv, const float* __restrict__ beta,
                        const float* __restrict__ gamma, float* __restrict__ out) {
    const size_t r = blockIdx.x;
    const float bet = beta[0];
    const __half* wrow = wv + r * EMB;
    const __half* urow = uv + r * EMB;
    __shared__ float buf[EMB];
    float ss = 0.f;
    for (int i = threadIdx.x; i < EMB; i += blockDim.x) {
        float wq = __half2float(wrow[i]);
        float s = 1.0f / (1.0f + __expf(-bet * wq));
        float gq = wq * s * __half2float(urow[i]);
        buf[i] = gq; ss += gq * gq;
    }
    ss = blk_sum(ss);
    const float sc = rsqrtf(ss * (1.0f / EMB) + 1e-6f);
    for (int i = threadIdx.x; i < EMB; i += blockDim.x)
        out[r * EMB + i] = x2[r * EMB + i] + gamma[i] * buf[i] * sc;
}

// ---------------- launcher ----------------
extern "C" void kernel_launch(void* const* d_in, const int* in_sizes, int n_in,
                              void* d_out, int out_size) {
    const float* x     = (const float*)d_in[0];
    const float* Wq    = (const float*)d_in[1];
    const float* Wk    = (const float*)d_in[2];
    const float* Wv    = (const float*)d_in[3];
    const float* Wo    = (const float*)d_in[4];
    const float* ln_g  = (const float*)d_in[5];
    const float* ln_b  = (const float*)d_in[6];
    const float* rms_g = (const float*)d_in[7];
    const float* W0    = (const float*)d_in[8];
    const float* swW   = (const float*)d_in[9];
    const float* swV   = (const float*)d_in[10];
    const float* swb   = (const float*)d_in[11];
    const float* mrg   = (const float*)d_in[12];
    float* out = (float*)d_out;

    __half *xh, *wh, *qkv, *vp, *cth, *x2h, *hh, *wuh;
    float *ctx, *xa;
    cudaGetSymbolAddress((void**)&xh,  g_xh);
    cudaGetSymbolAddress((void**)&wh,  g_wh);
    cudaGetSymbolAddress((void**)&qkv, g_qkvh);
    cudaGetSymbolAddress((void**)&vp,  g_vp);
    cudaGetSymbolAddress((void**)&ctx, g_ctx);
    cudaGetSymbolAddress((void**)&cth, g_cth);
    cudaGetSymbolAddress((void**)&xa,  g_xa);
    cudaGetSymbolAddress((void**)&x2h, g_x2h);
    cudaGetSymbolAddress((void**)&hh,  g_hh);
    cudaGetSymbolAddress((void**)&wuh, g_wuh);

    __half* qh = qkv + 0 * PLANE;
    __half* kh = qkv + 1 * PLANE;
    __half* v  = qkv + 2 * PLANE;
    __half* wvh = wuh + 0 * PLANE;
    __half* uvh = wuh + 1 * PLANE;
    const long long NW = (long long)EMB * EMB;

    cudaFuncSetAttribute(gemm_h<2,false>, cudaFuncAttributeMaxDynamicSharedMemorySize, SMEM_GEMM);
    cudaFuncSetAttribute(gemm_h<0,true >, cudaFuncAttributeMaxDynamicSharedMemorySize, SMEM_GEMM);
    cudaFuncSetAttribute(gemm_h<1,false>, cudaFuncAttributeMaxDynamicSharedMemorySize, SMEM_GEMM);
    cudaFuncSetAttribute(attn_fused128,   cudaFuncAttributeMaxDynamicSharedMemorySize, SMEM_ATT);

    const float scale = 0.08838834764831845f;  // 1/sqrt(128)
    const int NEW = MTOT * EMB;                // 8,388,608
    dim3 blk(256);

    // fp32 -> fp16 operand conversions
    f2h_k<<<NEW / 1024, 256>>>(x, xh);
    W7 ws; ws.p[0]=Wq; ws.p[1]=Wk; ws.p[2]=Wv; ws.p[3]=Wo; ws.p[4]=W0; ws.p[5]=swW; ws.p[6]=swV;
    f2h7_k<<<dim3(NW / 1024, 7), 256>>>(ws, wh);

    // merged QKV projection: z selects weight plane + output plane
    dim3 gqkv(EMB / BN, MTOT / BM, 3);         // (16,32,3)
    gemm_h<2,false><<<gqkv, blk, SMEM_GEMM>>>(64,
        xh, EMB, 0, wh, EMB, EMB, nullptr, qkv, EMB, nullptr, 1.0f, scale, 0);

    repack_v_t<<<dim3(16, 32, 2), 256>>>(v, vp);

    // fused attention: QK^T + causal softmax + PV -> ctx fp32 (128x64 tiles)
    attn_fused128<<<512, blk, SMEM_ATT>>>(qh, kh, vp, ctx);

    layernorm_h<<<MTOT, 256>>>(ctx, cth, ln_g, ln_b);

    // xa = x + cth @ Wo^T (fp32, residual fused via accumulator init)
    dim3 gp(EMB / BN, MTOT / BM, 1);           // (16,32,1)
    gemm_h<0,true><<<gp, blk, SMEM_GEMM>>>(64,
        cth, EMB, 0, wh + 3 * NW, EMB, 0, xa, nullptr, EMB, x, 1.0f, 1.0f, 0);

    rmsnorm_dual<<<MTOT, 256>>>(xa, x2h, rms_g);

    // h = x2 @ W0^T (half out)
    gemm_h<1,false><<<gp, blk, SMEM_GEMM>>>(64,
        x2h, EMB, 0, wh + 4 * NW, EMB, 0, nullptr, hh, EMB, nullptr, 1.0f, 1.0f, 0);

    // merged swW/swV: z selects weight plane + half output plane
    dim3 gsw(EMB / BN, MTOT / BM, 2);          // (16,32,2)
    gemm_h<1,false><<<gsw, blk, SMEM_GEMM>>>(64,
        hh, EMB, 0, wh + 5 * NW, EMB, EMB, nullptr, wuh, EMB, nullptr, 1.0f, 1.0f,
        (long long)PLANE);

    final_k<<<MTOT, 256>>>(xa, wvh, uvh, swb, mrg, out);   // swiglu + rmsnorm + residual
}